// round 4
// baseline (speedup 1.0000x reference)
#include <cuda_runtime.h>
#include <cuda_bf16.h>
#include <math.h>

#define NN 50000
#define EE 800000
#define ET 850000   // EE + NN self loops
#define IN_DIM 128
#define HID 128
#define HEADS 8
#define OUT_DIM 64
#define NEG_SLOPE 0.2f

// ---------------- scratch (device globals; no allocation) ----------------
__device__ __align__(16) float g_h1[NN * HID];
__device__ __align__(16) float g_a1s[NN * HEADS];
__device__ __align__(16) float g_a1d[NN * HEADS];
__device__ __align__(16) float g_den1[NN * HEADS];
__device__ __align__(16) float g_ex1[(size_t)ET * HEADS];
__device__ __align__(16) float g_out1[NN * HID];
__device__ __align__(16) float g_h2[NN * OUT_DIM];
__device__ __align__(16) float g_a2s[NN];
__device__ __align__(16) float g_a2d[NN];
__device__ __align__(16) float g_den2[NN];
__device__ __align__(16) float g_ex2[ET];
__device__ __align__(16) float g_out2[NN * OUT_DIM];
__device__ int g_src[ET];
__device__ int g_dst[ET];
__device__ int g_is64;

// ---------------- helpers ----------------
__device__ __forceinline__ void red_add_v4(float* p, float a, float b, float c, float d) {
    asm volatile("red.global.add.v4.f32 [%0], {%1, %2, %3, %4};"
                 :: "l"(p), "f"(a), "f"(b), "f"(c), "f"(d) : "memory");
}
__device__ __forceinline__ void red_add_v2(float* p, float a, float b) {
    asm volatile("red.global.add.v2.f32 [%0], {%1, %2};"
                 :: "l"(p), "f"(a), "f"(b) : "memory");
}
__device__ __forceinline__ float leaky(float e) {
    return e > 0.f ? e : NEG_SLOPE * e;
}

// ---------------- K0a: detect edge_index dtype (int64 vs int32) ----------------
__global__ void k0_detect(const long long* __restrict__ ei) {
    __shared__ int bad;
    if (threadIdx.x == 0) bad = 0;
    __syncthreads();
    for (int i = threadIdx.x; i < 256; i += blockDim.x) {
        long long v = ei[i];
        if (v < 0 || v >= (long long)NN) bad = 1;
    }
    __syncthreads();
    if (threadIdx.x == 0) g_is64 = bad ? 0 : 1;
}

// ---------------- K0b: decode edges (+self loops) into flat int arrays ----------
__global__ void k0_decode(const void* __restrict__ eiv) {
    const int i = blockIdx.x * blockDim.x + threadIdx.x;
    if (i >= ET) return;
    int s, d;
    if (i >= EE) {
        s = d = i - EE;
    } else if (g_is64) {
        const long long* e = (const long long*)eiv;
        s = (int)e[i]; d = (int)e[EE + i];
    } else {
        const int* e = (const int*)eiv;
        s = e[i]; d = e[EE + i];
    }
    g_src[i] = s;
    g_dst[i] = d;
}

// ---------------- K1: h1 = x @ W1  + per-head attention dots ----------------
// block = 128 threads, 8 nodes per block.
__global__ void k1_gemm1(const float* __restrict__ x, const float* __restrict__ W1,
                         const float* __restrict__ as1, const float* __restrict__ ad1) {
    __shared__ float xs[8][IN_DIM];
    const int t = threadIdx.x;
    const int n0 = blockIdx.x * 8;
    const int nn = min(8, NN - n0);

    for (int i = t; i < nn * IN_DIM; i += 128)
        xs[i >> 7][i & 127] = x[n0 * IN_DIM + i];
    __syncthreads();

    float acc[8];
#pragma unroll
    for (int j = 0; j < 8; j++) acc[j] = 0.f;

#pragma unroll 8
    for (int k = 0; k < IN_DIM; k++) {
        const float w = W1[k * HID + t];
#pragma unroll
        for (int j = 0; j < 8; j++) acc[j] += xs[j][k] * w;
    }

    const float vas = as1[t], vad = ad1[t];
#pragma unroll
    for (int j = 0; j < 8; j++) {
        if (j < nn) {
            g_h1[(n0 + j) * HID + t] = acc[j];
            float vs = acc[j] * vas, vd = acc[j] * vad;
#pragma unroll
            for (int o = 8; o; o >>= 1) {
                vs += __shfl_xor_sync(0xffffffffu, vs, o);
                vd += __shfl_xor_sync(0xffffffffu, vd, o);
            }
            if ((t & 15) == 0) {
                g_a1s[(n0 + j) * HEADS + (t >> 4)] = vs;
                g_a1d[(n0 + j) * HEADS + (t >> 4)] = vd;
            }
        }
    }
}

// ---------------- K2: edge logits layer1: exp + denom accumulate ----------------
__global__ void k2_edge1() {
    const int idx = blockIdx.x * blockDim.x + threadIdx.x;
    if (idx >= ET) return;
    const int s = g_src[idx], d = g_dst[idx];

    const float4 s0 = *(const float4*)&g_a1s[s * HEADS];
    const float4 s1 = *(const float4*)&g_a1s[s * HEADS + 4];
    const float4 d0 = *(const float4*)&g_a1d[d * HEADS];
    const float4 d1 = *(const float4*)&g_a1d[d * HEADS + 4];

    float e0 = __expf(leaky(s0.x + d0.x));
    float e1 = __expf(leaky(s0.y + d0.y));
    float e2 = __expf(leaky(s0.z + d0.z));
    float e3 = __expf(leaky(s0.w + d0.w));
    float e4 = __expf(leaky(s1.x + d1.x));
    float e5 = __expf(leaky(s1.y + d1.y));
    float e6 = __expf(leaky(s1.z + d1.z));
    float e7 = __expf(leaky(s1.w + d1.w));

    float4* pe = (float4*)&g_ex1[(size_t)idx * HEADS];
    pe[0] = make_float4(e0, e1, e2, e3);
    pe[1] = make_float4(e4, e5, e6, e7);

    red_add_v4(&g_den1[d * HEADS], e0, e1, e2, e3);
    red_add_v4(&g_den1[d * HEADS + 4], e4, e5, e6, e7);
}

// ---------------- K3: layer1 message aggregation (warp per edge) ----------------
__global__ void k3_agg1() {
    const int warp = (blockIdx.x * blockDim.x + threadIdx.x) >> 5;
    const int lane = threadIdx.x & 31;
    if (warp >= ET) return;
    const int s = g_src[warp], d = g_dst[warp];

    const int h = lane >> 2;  // 4 lanes per head * 4 ch each == 16 ch/head
    const float alpha = g_ex1[(size_t)warp * HEADS + h] /
                        (g_den1[d * HEADS + h] + 1e-16f);
    const float4 hv = *(const float4*)&g_h1[s * HID + lane * 4];
    red_add_v4(&g_out1[d * HID + lane * 4],
               hv.x * alpha, hv.y * alpha, hv.z * alpha, hv.w * alpha);
}

// ---------------- K4: h2 = elu(out1 + b1) @ W2 + attention dots ----------------
// block = 64 threads, 8 nodes per block.
__global__ void k4_gemm2(const float* __restrict__ W2, const float* __restrict__ b1,
                         const float* __restrict__ as2, const float* __restrict__ ad2) {
    __shared__ float hs[8][HID];
    __shared__ float rb[2][16];
    const int t = threadIdx.x;
    const int n0 = blockIdx.x * 8;
    const int nn = min(8, NN - n0);

    for (int i = t; i < nn * HID; i += 64) {
        const int k = i & 127;
        float v = g_out1[n0 * HID + i] + b1[k];
        hs[i >> 7][k] = v > 0.f ? v : (__expf(v) - 1.f);
    }
    __syncthreads();

    float acc[8];
#pragma unroll
    for (int j = 0; j < 8; j++) acc[j] = 0.f;

#pragma unroll 8
    for (int k = 0; k < HID; k++) {
        const float w = W2[k * OUT_DIM + t];
#pragma unroll
        for (int j = 0; j < 8; j++) acc[j] += hs[j][k] * w;
    }

    const float vas = as2[t], vad = ad2[t];
    const int wid = t >> 5;
#pragma unroll
    for (int j = 0; j < 8; j++) {
        if (j < nn) g_h2[(n0 + j) * OUT_DIM + t] = acc[j];
        float vs = acc[j] * vas, vd = acc[j] * vad;
#pragma unroll
        for (int o = 16; o; o >>= 1) {
            vs += __shfl_xor_sync(0xffffffffu, vs, o);
            vd += __shfl_xor_sync(0xffffffffu, vd, o);
        }
        if ((t & 31) == 0) { rb[wid][j * 2] = vs; rb[wid][j * 2 + 1] = vd; }
        __syncthreads();
        if (t == 0 && j < nn) {
            g_a2s[n0 + j] = rb[0][j * 2] + rb[1][j * 2];
            g_a2d[n0 + j] = rb[0][j * 2 + 1] + rb[1][j * 2 + 1];
        }
        __syncthreads();
    }
}

// ---------------- K5: edge logits layer2 ----------------
__global__ void k5_edge2() {
    const int idx = blockIdx.x * blockDim.x + threadIdx.x;
    if (idx >= ET) return;
    const int s = g_src[idx], d = g_dst[idx];
    const float ex = __expf(leaky(g_a2s[s] + g_a2d[d]));
    g_ex2[idx] = ex;
    atomicAdd(&g_den2[d], ex);
}

// ---------------- K6: layer2 message aggregation (warp per edge) ----------------
__global__ void k6_agg2() {
    const int warp = (blockIdx.x * blockDim.x + threadIdx.x) >> 5;
    const int lane = threadIdx.x & 31;
    if (warp >= ET) return;
    const int s = g_src[warp], d = g_dst[warp];
    const float alpha = g_ex2[warp] / (g_den2[d] + 1e-16f);
    const float2 hv = *(const float2*)&g_h2[s * OUT_DIM + lane * 2];
    red_add_v2(&g_out2[d * OUT_DIM + lane * 2], hv.x * alpha, hv.y * alpha);
}

// ---------------- K7: log_softmax over 64 (warp per node) ----------------
__global__ void k7_lsm(const float* __restrict__ b2, float* __restrict__ out) {
    const int n = (blockIdx.x * blockDim.x + threadIdx.x) >> 5;
    const int lane = threadIdx.x & 31;
    if (n >= NN) return;
    float2 v = *(const float2*)&g_out2[n * OUT_DIM + lane * 2];
    v.x += b2[lane * 2];
    v.y += b2[lane * 2 + 1];
    float m = fmaxf(v.x, v.y);
#pragma unroll
    for (int o = 16; o; o >>= 1) m = fmaxf(m, __shfl_xor_sync(0xffffffffu, m, o));
    float ssum = expf(v.x - m) + expf(v.y - m);
#pragma unroll
    for (int o = 16; o; o >>= 1) ssum += __shfl_xor_sync(0xffffffffu, ssum, o);
    const float lse = m + logf(ssum);
    float2 r = make_float2(v.x - lse, v.y - lse);
    *(float2*)&out[n * OUT_DIM + lane * 2] = r;
}

// ---------------- launch ----------------
extern "C" void kernel_launch(void* const* d_in, const int* in_sizes, int n_in,
                              void* d_out, int out_size) {
    const float* x   = (const float*)d_in[0];
    const void*  ei  = d_in[1];
    const float* W1  = (const float*)d_in[2];
    const float* as1 = (const float*)d_in[3];
    const float* ad1 = (const float*)d_in[4];
    const float* b1  = (const float*)d_in[5];
    const float* W2  = (const float*)d_in[6];
    const float* as2 = (const float*)d_in[7];
    const float* ad2 = (const float*)d_in[8];
    const float* b2  = (const float*)d_in[9];
    float* out = (float*)d_out;

    void *pden1, *pout1, *pden2, *pout2;
    cudaGetSymbolAddress(&pden1, g_den1);
    cudaGetSymbolAddress(&pout1, g_out1);
    cudaGetSymbolAddress(&pden2, g_den2);
    cudaGetSymbolAddress(&pout2, g_out2);
    cudaMemsetAsync(pden1, 0, sizeof(float) * NN * HEADS);
    cudaMemsetAsync(pout1, 0, sizeof(float) * NN * HID);
    cudaMemsetAsync(pden2, 0, sizeof(float) * NN);
    cudaMemsetAsync(pout2, 0, sizeof(float) * NN * OUT_DIM);

    k0_detect<<<1, 256>>>((const long long*)ei);
    k0_decode<<<(ET + 255) / 256, 256>>>(ei);
    k1_gemm1<<<(NN + 7) / 8, 128>>>(x, W1, as1, ad1);
    k2_edge1<<<(ET + 255) / 256, 256>>>();
    k3_agg1<<<(ET + 7) / 8, 256>>>();
    k4_gemm2<<<(NN + 7) / 8, 64>>>(W2, b1, as2, ad2);
    k5_edge2<<<(ET + 255) / 256, 256>>>();
    k6_agg2<<<(ET + 7) / 8, 256>>>();
    k7_lsm<<<(NN + 7) / 8, 256>>>(b2, out);
}

// round 5
// speedup vs baseline: 1.6748x; 1.6748x over previous
#include <cuda_runtime.h>
#include <cuda_bf16.h>
#include <math.h>

#define NN 50000
#define EE 800000
#define ET 850000   // EE + NN self loops
#define IN_DIM 128
#define HID 128
#define HEADS 8
#define OUT_DIM 64
#define NEG_SLOPE 0.2f

// ---------------- scratch (device globals; no allocation) ----------------
__device__ __align__(16) float g_h1[NN * HID];
__device__ __align__(16) float g_a1s[NN * HEADS];
__device__ __align__(16) float g_a1d[NN * HEADS];
__device__ __align__(16) float g_den1[NN * HEADS];
__device__ __align__(16) float g_out1[NN * HID];     // UNNORMALIZED layer1 agg
__device__ __align__(16) float g_h2[NN * OUT_DIM];
__device__ __align__(16) float g_a2s[NN];
__device__ __align__(16) float g_a2d[NN];
__device__ __align__(16) float g_den2[NN];
__device__ __align__(16) float g_out2[NN * OUT_DIM]; // UNNORMALIZED layer2 agg
__device__ __align__(8)  int2  g_edge[ET];           // (src, dst)
__device__ int g_is64;

// ---------------- helpers ----------------
__device__ __forceinline__ void red_add_v4(float* p, float a, float b, float c, float d) {
    asm volatile("red.global.add.v4.f32 [%0], {%1, %2, %3, %4};"
                 :: "l"(p), "f"(a), "f"(b), "f"(c), "f"(d) : "memory");
}
__device__ __forceinline__ float leaky(float e) {
    return e > 0.f ? e : NEG_SLOPE * e;
}

// ---------------- K0a: detect edge_index dtype (int64 vs int32) ----------------
__global__ void k0_detect(const long long* __restrict__ ei) {
    __shared__ int bad;
    if (threadIdx.x == 0) bad = 0;
    __syncthreads();
    for (int i = threadIdx.x; i < 256; i += blockDim.x) {
        long long v = ei[i];
        if (v < 0 || v >= (long long)NN) bad = 1;
    }
    __syncthreads();
    if (threadIdx.x == 0) g_is64 = bad ? 0 : 1;
}

// ---------------- K0b: decode edges (+self loops) into packed int2 ----------
__global__ void k0_decode(const void* __restrict__ eiv) {
    const int i = blockIdx.x * blockDim.x + threadIdx.x;
    if (i >= ET) return;
    int s, d;
    if (i >= EE) {
        s = d = i - EE;
    } else if (g_is64) {
        const long long* e = (const long long*)eiv;
        s = (int)e[i]; d = (int)e[EE + i];
    } else {
        const int* e = (const int*)eiv;
        s = e[i]; d = e[EE + i];
    }
    g_edge[i] = make_int2(s, d);
}

// ---------------- K1: h1 = x @ W1  + per-head attention dots ----------------
// block = 128 threads, 8 nodes per block.
__global__ void k1_gemm1(const float* __restrict__ x, const float* __restrict__ W1,
                         const float* __restrict__ as1, const float* __restrict__ ad1) {
    __shared__ float xs[8][IN_DIM];
    const int t = threadIdx.x;
    const int n0 = blockIdx.x * 8;
    const int nn = min(8, NN - n0);

    for (int i = t; i < nn * IN_DIM; i += 128)
        xs[i >> 7][i & 127] = x[n0 * IN_DIM + i];
    __syncthreads();

    float acc[8];
#pragma unroll
    for (int j = 0; j < 8; j++) acc[j] = 0.f;

#pragma unroll 8
    for (int k = 0; k < IN_DIM; k++) {
        const float w = W1[k * HID + t];
#pragma unroll
        for (int j = 0; j < 8; j++) acc[j] += xs[j][k] * w;
    }

    const float vas = as1[t], vad = ad1[t];
#pragma unroll
    for (int j = 0; j < 8; j++) {
        if (j < nn) {
            g_h1[(n0 + j) * HID + t] = acc[j];
            float vs = acc[j] * vas, vd = acc[j] * vad;
#pragma unroll
            for (int o = 8; o; o >>= 1) {
                vs += __shfl_xor_sync(0xffffffffu, vs, o);
                vd += __shfl_xor_sync(0xffffffffu, vd, o);
            }
            if ((t & 15) == 0) {
                g_a1s[(n0 + j) * HEADS + (t >> 4)] = vs;
                g_a1d[(n0 + j) * HEADS + (t >> 4)] = vd;
            }
        }
    }
}

// ---------------- K23: fused layer1 edge pass (exp + den + UNNORM aggregation) ---
// warp per edge; lane handles 4 channels (head = lane>>2).
__global__ void k23_edge_agg1() {
    const int warp = (blockIdx.x * blockDim.x + threadIdx.x) >> 5;
    const int lane = threadIdx.x & 31;
    if (warp >= ET) return;
    const int2 sd = g_edge[warp];
    const int s = sd.x, d = sd.y;

    // lanes 0..7 compute the 8 per-head exp values
    float e = 0.f;
    if (lane < 8)
        e = __expf(leaky(g_a1s[s * HEADS + lane] + g_a1d[d * HEADS + lane]));

    // broadcast to all lanes of this head
    const float exh = __shfl_sync(0xffffffffu, e, lane >> 2);

    // denominator: lanes 0 and 1 each push a v4 (heads 0-3, 4-7)
    const int base = (lane * 4) & 31;
    const float a0 = __shfl_sync(0xffffffffu, e, base);
    const float a1 = __shfl_sync(0xffffffffu, e, base + 1);
    const float a2 = __shfl_sync(0xffffffffu, e, base + 2);
    const float a3 = __shfl_sync(0xffffffffu, e, base + 3);
    if (lane < 2)
        red_add_v4(&g_den1[d * HEADS + lane * 4], a0, a1, a2, a3);

    // unnormalized message
    const float4 hv = *(const float4*)&g_h1[s * HID + lane * 4];
    red_add_v4(&g_out1[d * HID + lane * 4],
               hv.x * exh, hv.y * exh, hv.z * exh, hv.w * exh);
}

// ---------------- K4: h2 = elu(out1/den1 + b1) @ W2 + attention dots ----------
// block = 64 threads, 8 nodes per block.
__global__ void k4_gemm2(const float* __restrict__ W2, const float* __restrict__ b1,
                         const float* __restrict__ as2, const float* __restrict__ ad2) {
    __shared__ float hs[8][HID];
    __shared__ float rb[2][16];
    const int t = threadIdx.x;
    const int n0 = blockIdx.x * 8;
    const int nn = min(8, NN - n0);

    for (int i = t; i < nn * HID; i += 64) {
        const int j = i >> 7, k = i & 127;
        const float den = g_den1[(n0 + j) * HEADS + (k >> 4)] + 1e-16f;
        float v = g_out1[n0 * HID + i] / den + b1[k];
        hs[j][k] = v > 0.f ? v : (__expf(v) - 1.f);
    }
    __syncthreads();

    float acc[8];
#pragma unroll
    for (int j = 0; j < 8; j++) acc[j] = 0.f;

#pragma unroll 8
    for (int k = 0; k < HID; k++) {
        const float w = W2[k * OUT_DIM + t];
#pragma unroll
        for (int j = 0; j < 8; j++) acc[j] += hs[j][k] * w;
    }

    const float vas = as2[t], vad = ad2[t];
    const int wid = t >> 5;
#pragma unroll
    for (int j = 0; j < 8; j++) {
        if (j < nn) g_h2[(n0 + j) * OUT_DIM + t] = acc[j];
        float vs = acc[j] * vas, vd = acc[j] * vad;
#pragma unroll
        for (int o = 16; o; o >>= 1) {
            vs += __shfl_xor_sync(0xffffffffu, vs, o);
            vd += __shfl_xor_sync(0xffffffffu, vd, o);
        }
        if ((t & 31) == 0) { rb[wid][j * 2] = vs; rb[wid][j * 2 + 1] = vd; }
        __syncthreads();
        if (t == 0 && j < nn) {
            g_a2s[n0 + j] = rb[0][j * 2] + rb[1][j * 2];
            g_a2d[n0 + j] = rb[0][j * 2 + 1] + rb[1][j * 2 + 1];
        }
        __syncthreads();
    }
}

// ---------------- K56: fused layer2 edge pass (2 edges per warp, red.v4) -------
__global__ void k56_edge_agg2() {
    const int warp = (blockIdx.x * blockDim.x + threadIdx.x) >> 5;
    const int lane = threadIdx.x & 31;
    const int eid = warp * 2 + (lane >> 4);
    const int sub = lane & 15;
    if (eid >= ET) return;
    const int2 sd = g_edge[eid];
    const int s = sd.x, d = sd.y;

    float e = 0.f;
    if (sub == 0)
        e = __expf(leaky(g_a2s[s] + g_a2d[d]));
    const float ex = __shfl_sync(0xffffffffu, e, lane & 16);
    if (sub == 0)
        atomicAdd(&g_den2[d], ex);

    const float4 hv = *(const float4*)&g_h2[s * OUT_DIM + sub * 4];
    red_add_v4(&g_out2[d * OUT_DIM + sub * 4],
               hv.x * ex, hv.y * ex, hv.z * ex, hv.w * ex);
}

// ---------------- K7: normalize + bias + log_softmax (warp per node) ----------
__global__ void k7_lsm(const float* __restrict__ b2, float* __restrict__ out) {
    const int n = (blockIdx.x * blockDim.x + threadIdx.x) >> 5;
    const int lane = threadIdx.x & 31;
    if (n >= NN) return;
    const float inv_den = 1.f / (g_den2[n] + 1e-16f);
    float2 v = *(const float2*)&g_out2[n * OUT_DIM + lane * 2];
    v.x = v.x * inv_den + b2[lane * 2];
    v.y = v.y * inv_den + b2[lane * 2 + 1];
    float m = fmaxf(v.x, v.y);
#pragma unroll
    for (int o = 16; o; o >>= 1) m = fmaxf(m, __shfl_xor_sync(0xffffffffu, m, o));
    float ssum = expf(v.x - m) + expf(v.y - m);
#pragma unroll
    for (int o = 16; o; o >>= 1) ssum += __shfl_xor_sync(0xffffffffu, ssum, o);
    const float lse = m + logf(ssum);
    float2 r = make_float2(v.x - lse, v.y - lse);
    *(float2*)&out[n * OUT_DIM + lane * 2] = r;
}

// ---------------- launch ----------------
extern "C" void kernel_launch(void* const* d_in, const int* in_sizes, int n_in,
                              void* d_out, int out_size) {
    const float* x   = (const float*)d_in[0];
    const void*  ei  = d_in[1];
    const float* W1  = (const float*)d_in[2];
    const float* as1 = (const float*)d_in[3];
    const float* ad1 = (const float*)d_in[4];
    const float* b1  = (const float*)d_in[5];
    const float* W2  = (const float*)d_in[6];
    const float* as2 = (const float*)d_in[7];
    const float* ad2 = (const float*)d_in[8];
    const float* b2  = (const float*)d_in[9];
    float* out = (float*)d_out;

    void *pden1, *pout1, *pden2, *pout2;
    cudaGetSymbolAddress(&pden1, g_den1);
    cudaGetSymbolAddress(&pout1, g_out1);
    cudaGetSymbolAddress(&pden2, g_den2);
    cudaGetSymbolAddress(&pout2, g_out2);
    cudaMemsetAsync(pden1, 0, sizeof(float) * NN * HEADS);
    cudaMemsetAsync(pout1, 0, sizeof(float) * NN * HID);
    cudaMemsetAsync(pden2, 0, sizeof(float) * NN);
    cudaMemsetAsync(pout2, 0, sizeof(float) * NN * OUT_DIM);

    k0_detect<<<1, 256>>>((const long long*)ei);
    k0_decode<<<(ET + 255) / 256, 256>>>(ei);
    k1_gemm1<<<(NN + 7) / 8, 128>>>(x, W1, as1, ad1);
    k23_edge_agg1<<<(ET + 7) / 8, 256>>>();
    k4_gemm2<<<(NN + 7) / 8, 64>>>(W2, b1, as2, ad2);
    k56_edge_agg2<<<(ET / 2 + 7) / 8, 256>>>();
    k7_lsm<<<(NN + 7) / 8, 256>>>(b2, out);
}

// round 6
// speedup vs baseline: 1.7773x; 1.0612x over previous
#include <cuda_runtime.h>
#include <cuda_bf16.h>
#include <math.h>

#define NN 50000
#define EE 800000
#define ET 850000   // EE + NN self loops
#define IN_DIM 128
#define HID 128
#define HEADS 8
#define OUT_DIM 64
#define NEG_SLOPE 0.2f
#define SCAN_T 1024
#define SCAN_CHUNK 49   // 1024*49 = 50176 >= NN

// ---------------- scratch (device globals; no allocation) ----------------
__device__ __align__(16) float g_h1[NN * HID];
__device__ __align__(16) float g_a1s[NN * HEADS];
__device__ __align__(16) float g_a1d[NN * HEADS];
__device__ __align__(16) float g_out1[NN * HID];     // normalized layer1 agg
__device__ __align__(16) float g_h2[NN * OUT_DIM];
__device__ __align__(16) float g_a2s[NN];
__device__ __align__(16) float g_a2d[NN];
__device__ __align__(16) float g_out2[NN * OUT_DIM]; // normalized layer2 agg
__device__ __align__(8)  int2  g_edge[ET];           // (src, dst)
__device__ int g_deg[NN];
__device__ int g_ptr[NN + 1];
__device__ int g_pos[NN];
__device__ int g_srcs[ET];                           // src sorted by dst
__device__ int g_is64;

__device__ __forceinline__ float leaky(float e) {
    return e > 0.f ? e : NEG_SLOPE * e;
}

// ---------------- K0a: detect edge_index dtype (int64 vs int32) ----------------
__global__ void k0_detect(const long long* __restrict__ ei) {
    __shared__ int bad;
    if (threadIdx.x == 0) bad = 0;
    __syncthreads();
    for (int i = threadIdx.x; i < 256; i += blockDim.x) {
        long long v = ei[i];
        if (v < 0 || v >= (long long)NN) bad = 1;
    }
    __syncthreads();
    if (threadIdx.x == 0) g_is64 = bad ? 0 : 1;
}

// ---------------- K0b: decode edges (+self loops) + degree histogram ----------
__global__ void k0_decode(const void* __restrict__ eiv) {
    const int i = blockIdx.x * blockDim.x + threadIdx.x;
    if (i >= ET) return;
    int s, d;
    if (i >= EE) {
        s = d = i - EE;
    } else if (g_is64) {
        const long long* e = (const long long*)eiv;
        s = (int)e[i]; d = (int)e[EE + i];
    } else {
        const int* e = (const int*)eiv;
        s = e[i]; d = e[EE + i];
    }
    g_edge[i] = make_int2(s, d);
    atomicAdd(&g_deg[d], 1);
}

// ---------------- K0c: exclusive scan of degrees (single block) ---------------
__global__ void k0_scan() {
    __shared__ int partial[SCAN_T];
    const int t = threadIdx.x;
    const int start = t * SCAN_CHUNK;
    const int end = min(start + SCAN_CHUNK, NN);
    int sum = 0;
    for (int i = start; i < end; i++) sum += g_deg[i];
    partial[t] = sum;
    __syncthreads();
    for (int dd = 1; dd < SCAN_T; dd <<= 1) {
        int v = (t >= dd) ? partial[t - dd] : 0;
        __syncthreads();
        partial[t] += v;
        __syncthreads();
    }
    int off = partial[t] - sum;  // exclusive prefix
    for (int i = start; i < end; i++) {
        g_ptr[i] = off;
        g_pos[i] = off;
        off += g_deg[i];
    }
    if (t == SCAN_T - 1) g_ptr[NN] = partial[SCAN_T - 1];
}

// ---------------- K0d: scatter srcs into dst-sorted order ---------------------
__global__ void k0_scatter() {
    const int i = blockIdx.x * blockDim.x + threadIdx.x;
    if (i >= ET) return;
    const int2 sd = g_edge[i];
    const int p = atomicAdd(&g_pos[sd.y], 1);
    g_srcs[p] = sd.x;
}

// ---------------- K1: h1 = x @ W1  + per-head attention dots ----------------
// block = 128 threads, 8 nodes per block.
__global__ void k1_gemm1(const float* __restrict__ x, const float* __restrict__ W1,
                         const float* __restrict__ as1, const float* __restrict__ ad1) {
    __shared__ float xs[8][IN_DIM];
    const int t = threadIdx.x;
    const int n0 = blockIdx.x * 8;
    const int nn = min(8, NN - n0);

    for (int i = t; i < nn * IN_DIM; i += 128)
        xs[i >> 7][i & 127] = x[n0 * IN_DIM + i];
    __syncthreads();

    float acc[8];
#pragma unroll
    for (int j = 0; j < 8; j++) acc[j] = 0.f;

#pragma unroll 8
    for (int k = 0; k < IN_DIM; k++) {
        const float w = W1[k * HID + t];
#pragma unroll
        for (int j = 0; j < 8; j++) acc[j] += xs[j][k] * w;
    }

    const float vas = as1[t], vad = ad1[t];
#pragma unroll
    for (int j = 0; j < 8; j++) {
        if (j < nn) {
            g_h1[(n0 + j) * HID + t] = acc[j];
            float vs = acc[j] * vas, vd = acc[j] * vad;
#pragma unroll
            for (int o = 8; o; o >>= 1) {
                vs += __shfl_xor_sync(0xffffffffu, vs, o);
                vd += __shfl_xor_sync(0xffffffffu, vd, o);
            }
            if ((t & 15) == 0) {
                g_a1s[(n0 + j) * HEADS + (t >> 4)] = vs;
                g_a1d[(n0 + j) * HEADS + (t >> 4)] = vd;
            }
        }
    }
}

// ---------------- K3: CSR layer1 aggregation (warp per dst node) --------------
// lane handles 4 channels of head (lane>>2); lanes 0-7 own per-head exp/den.
__global__ void k3_agg1() {
    const int d = (blockIdx.x * blockDim.x + threadIdx.x) >> 5;
    const int lane = threadIdx.x & 31;
    if (d >= NN) return;

    float a1d_h = 0.f;
    if (lane < 8) a1d_h = g_a1d[d * HEADS + lane];

    const int p0 = g_ptr[d], p1 = g_ptr[d + 1];
    float4 acc = make_float4(0.f, 0.f, 0.f, 0.f);
    float densum = 0.f;   // lanes 0-7: full denominator for head `lane`

    for (int base = p0; base < p1; base += 32) {
        const int cnt = min(32, p1 - base);
        int s_r = 0;
        if (lane < cnt) s_r = __ldg(&g_srcs[base + lane]);
        for (int j = 0; j < cnt; j++) {
            const int s = __shfl_sync(0xffffffffu, s_r, j);
            float e = 0.f;
            if (lane < 8) {
                e = __expf(leaky(__ldg(&g_a1s[s * HEADS + lane]) + a1d_h));
                densum += e;
            }
            const float exh = __shfl_sync(0xffffffffu, e, lane >> 2);
            const float4 hv = *(const float4*)&g_h1[s * HID + lane * 4];
            acc.x += hv.x * exh;
            acc.y += hv.y * exh;
            acc.z += hv.z * exh;
            acc.w += hv.w * exh;
        }
    }
    // denominator for my head lives in lane (lane>>2)
    const float den = __shfl_sync(0xffffffffu, densum, lane >> 2);
    const float inv = 1.f / (den + 1e-16f);
    acc.x *= inv; acc.y *= inv; acc.z *= inv; acc.w *= inv;
    *(float4*)&g_out1[d * HID + lane * 4] = acc;
}

// ---------------- K4: h2 = elu(out1 + b1) @ W2 + attention dots ----------
// block = 64 threads, 8 nodes per block.
__global__ void k4_gemm2(const float* __restrict__ W2, const float* __restrict__ b1,
                         const float* __restrict__ as2, const float* __restrict__ ad2) {
    __shared__ float hs[8][HID];
    __shared__ float rb[2][16];
    const int t = threadIdx.x;
    const int n0 = blockIdx.x * 8;
    const int nn = min(8, NN - n0);

    for (int i = t; i < nn * HID; i += 64) {
        const int j = i >> 7, k = i & 127;
        float v = g_out1[n0 * HID + i] + b1[k];
        hs[j][k] = v > 0.f ? v : (__expf(v) - 1.f);
    }
    __syncthreads();

    float acc[8];
#pragma unroll
    for (int j = 0; j < 8; j++) acc[j] = 0.f;

#pragma unroll 8
    for (int k = 0; k < HID; k++) {
        const float w = W2[k * OUT_DIM + t];
#pragma unroll
        for (int j = 0; j < 8; j++) acc[j] += hs[j][k] * w;
    }

    const float vas = as2[t], vad = ad2[t];
    const int wid = t >> 5;
#pragma unroll
    for (int j = 0; j < 8; j++) {
        if (j < nn) g_h2[(n0 + j) * OUT_DIM + t] = acc[j];
        float vs = acc[j] * vas, vd = acc[j] * vad;
#pragma unroll
        for (int o = 16; o; o >>= 1) {
            vs += __shfl_xor_sync(0xffffffffu, vs, o);
            vd += __shfl_xor_sync(0xffffffffu, vd, o);
        }
        if ((t & 31) == 0) { rb[wid][j * 2] = vs; rb[wid][j * 2 + 1] = vd; }
        __syncthreads();
        if (t == 0 && j < nn) {
            g_a2s[n0 + j] = rb[0][j * 2] + rb[1][j * 2];
            g_a2d[n0 + j] = rb[0][j * 2 + 1] + rb[1][j * 2 + 1];
        }
        __syncthreads();
    }
}

// ---------------- K6: CSR layer2 aggregation (warp per dst node) --------------
// lane handles 2 channels; exps distributed across all 32 lanes.
__global__ void k6_agg2() {
    const int d = (blockIdx.x * blockDim.x + threadIdx.x) >> 5;
    const int lane = threadIdx.x & 31;
    if (d >= NN) return;

    const float a2d_d = g_a2d[d];
    const int p0 = g_ptr[d], p1 = g_ptr[d + 1];
    float2 acc = make_float2(0.f, 0.f);
    float densum = 0.f;

    for (int base = p0; base < p1; base += 32) {
        const int cnt = min(32, p1 - base);
        int s_r = 0;
        float e_r = 0.f;
        if (lane < cnt) {
            s_r = __ldg(&g_srcs[base + lane]);
            e_r = __expf(leaky(__ldg(&g_a2s[s_r]) + a2d_d));
            densum += e_r;
        }
        for (int j = 0; j < cnt; j++) {
            const int s = __shfl_sync(0xffffffffu, s_r, j);
            const float ex = __shfl_sync(0xffffffffu, e_r, j);
            const float2 hv = *(const float2*)&g_h2[s * OUT_DIM + lane * 2];
            acc.x += hv.x * ex;
            acc.y += hv.y * ex;
        }
    }
#pragma unroll
    for (int o = 16; o; o >>= 1) densum += __shfl_xor_sync(0xffffffffu, densum, o);
    const float inv = 1.f / (densum + 1e-16f);
    acc.x *= inv; acc.y *= inv;
    *(float2*)&g_out2[d * OUT_DIM + lane * 2] = acc;
}

// ---------------- K7: bias + log_softmax (warp per node) ----------------------
__global__ void k7_lsm(const float* __restrict__ b2, float* __restrict__ out) {
    const int n = (blockIdx.x * blockDim.x + threadIdx.x) >> 5;
    const int lane = threadIdx.x & 31;
    if (n >= NN) return;
    float2 v = *(const float2*)&g_out2[n * OUT_DIM + lane * 2];
    v.x += b2[lane * 2];
    v.y += b2[lane * 2 + 1];
    float m = fmaxf(v.x, v.y);
#pragma unroll
    for (int o = 16; o; o >>= 1) m = fmaxf(m, __shfl_xor_sync(0xffffffffu, m, o));
    float ssum = expf(v.x - m) + expf(v.y - m);
#pragma unroll
    for (int o = 16; o; o >>= 1) ssum += __shfl_xor_sync(0xffffffffu, ssum, o);
    const float lse = m + logf(ssum);
    float2 r = make_float2(v.x - lse, v.y - lse);
    *(float2*)&out[n * OUT_DIM + lane * 2] = r;
}

// ---------------- launch ----------------
extern "C" void kernel_launch(void* const* d_in, const int* in_sizes, int n_in,
                              void* d_out, int out_size) {
    const float* x   = (const float*)d_in[0];
    const void*  ei  = d_in[1];
    const float* W1  = (const float*)d_in[2];
    const float* as1 = (const float*)d_in[3];
    const float* ad1 = (const float*)d_in[4];
    const float* b1  = (const float*)d_in[5];
    const float* W2  = (const float*)d_in[6];
    const float* as2 = (const float*)d_in[7];
    const float* ad2 = (const float*)d_in[8];
    const float* b2  = (const float*)d_in[9];
    float* out = (float*)d_out;

    void* pdeg;
    cudaGetSymbolAddress(&pdeg, g_deg);
    cudaMemsetAsync(pdeg, 0, sizeof(int) * NN);

    k0_detect<<<1, 256>>>((const long long*)ei);
    k0_decode<<<(ET + 255) / 256, 256>>>(ei);
    k0_scan<<<1, SCAN_T>>>();
    k0_scatter<<<(ET + 255) / 256, 256>>>();
    k1_gemm1<<<(NN + 7) / 8, 128>>>(x, W1, as1, ad1);
    k3_agg1<<<(NN + 7) / 8, 256>>>();
    k4_gemm2<<<(NN + 7) / 8, 64>>>(W2, b1, as2, ad2);
    k6_agg2<<<(NN + 7) / 8, 256>>>();
    k7_lsm<<<(NN + 7) / 8, 256>>>(b2, out);
}

// round 8
// speedup vs baseline: 1.9441x; 1.0939x over previous
#include <cuda_runtime.h>
#include <cuda_bf16.h>
#include <math.h>

#define NN 50000
#define EE 800000
#define ET 850000   // EE + NN self loops
#define IN_DIM 128
#define HID 128
#define HEADS 8
#define OUT_DIM 64
#define NEG_SLOPE 0.2f
#define SCAN_T 1024
#define SCAN_CHUNK 49   // 1024*49 = 50176 >= NN

// ---------------- scratch (device globals; no allocation) ----------------
__device__ __align__(16) float g_h1[NN * HID];
__device__ __align__(16) float g_a1s[NN * HEADS];
__device__ __align__(16) float g_a1d[NN * HEADS];
__device__ __align__(16) float g_out1[NN * HID];     // normalized layer1 agg
__device__ __align__(16) float g_h2[NN * OUT_DIM];
__device__ __align__(16) float g_a2s[NN];
__device__ __align__(16) float g_a2d[NN];
__device__ __align__(8)  int2  g_edge[ET];           // (src, dst)
__device__ int g_deg[NN];
__device__ int g_ptr[NN + 1];
__device__ int g_pos[NN];
__device__ int g_srcs[ET];                           // src sorted by dst
__device__ int g_is64;

__device__ __forceinline__ float leaky(float e) {
    return e > 0.f ? e : NEG_SLOPE * e;
}
// packed f32x2 FMA (FFMA2) — ptxas won't emit this on its own
__device__ __forceinline__ unsigned long long ffma2(unsigned long long a,
                                                    unsigned long long b,
                                                    unsigned long long c) {
    unsigned long long d;
    asm("fma.rn.f32x2 %0, %1, %2, %3;" : "=l"(d) : "l"(a), "l"(b), "l"(c));
    return d;
}
__device__ __forceinline__ unsigned long long pack2(float lo, float hi) {
    unsigned long long r;
    asm("mov.b64 %0, {%1, %2};" : "=l"(r) : "f"(lo), "f"(hi));
    return r;
}
__device__ __forceinline__ void unpack2(unsigned long long v, float& lo, float& hi) {
    asm("mov.b64 {%0, %1}, %2;" : "=f"(lo), "=f"(hi) : "l"(v));
}

// ---------------- K0a: detect edge_index dtype (int64 vs int32) ---------------
__global__ void k0_detect(const long long* __restrict__ ei) {
    __shared__ int bad;
    if (threadIdx.x == 0) bad = 0;
    __syncthreads();
    for (int i = threadIdx.x; i < 256; i += blockDim.x) {
        long long v = ei[i];
        if (v < 0 || v >= (long long)NN) bad = 1;
    }
    __syncthreads();
    if (threadIdx.x == 0) g_is64 = bad ? 0 : 1;
}

// ---------------- K0b: decode edges (+self loops) + degree histogram ----------
__global__ void k0_decode(const void* __restrict__ eiv) {
    const int i = blockIdx.x * blockDim.x + threadIdx.x;
    if (i >= ET) return;
    int s, d;
    if (i >= EE) {
        s = d = i - EE;
    } else if (g_is64) {
        const long long* e = (const long long*)eiv;
        s = (int)e[i]; d = (int)e[EE + i];
    } else {
        const int* e = (const int*)eiv;
        s = e[i]; d = e[EE + i];
    }
    g_edge[i] = make_int2(s, d);
    atomicAdd(&g_deg[d], 1);
}

// ---------------- K0c: exclusive scan of degrees (single block) ---------------
__global__ void k0_scan() {
    __shared__ int partial[SCAN_T];
    const int t = threadIdx.x;
    const int start = t * SCAN_CHUNK;
    const int end = min(start + SCAN_CHUNK, NN);
    int sum = 0;
    for (int i = start; i < end; i++) sum += g_deg[i];
    partial[t] = sum;
    __syncthreads();
    for (int dd = 1; dd < SCAN_T; dd <<= 1) {
        int v = (t >= dd) ? partial[t - dd] : 0;
        __syncthreads();
        partial[t] += v;
        __syncthreads();
    }
    int off = partial[t] - sum;  // exclusive prefix
    for (int i = start; i < end; i++) {
        g_ptr[i] = off;
        g_pos[i] = off;
        off += g_deg[i];
    }
    if (t == SCAN_T - 1) g_ptr[NN] = partial[SCAN_T - 1];
}

// ---------------- K0d: scatter srcs into dst-sorted order ---------------------
__global__ void k0_scatter() {
    const int i = blockIdx.x * blockDim.x + threadIdx.x;
    if (i >= ET) return;
    const int2 sd = g_edge[i];
    const int p = atomicAdd(&g_pos[sd.y], 1);
    g_srcs[p] = sd.x;
}

// ---------------- K1: h1 = x @ W1 (FFMA2) + per-head attention dots ----------
// 128 threads (= out channel), 8 nodes per block; xst transposed for f32x2.
__global__ void k1_gemm1(const float* __restrict__ x, const float* __restrict__ W1,
                         const float* __restrict__ as1, const float* __restrict__ ad1) {
    __shared__ __align__(16) float xst[IN_DIM][8];   // [k][node]
    const int t = threadIdx.x;
    const int n0 = blockIdx.x * 8;

    for (int i = t; i < 8 * IN_DIM; i += 128) {
        const int j = i >> 7, k = i & 127;
        xst[k][j] = x[n0 * IN_DIM + i];
    }
    __syncthreads();

    unsigned long long acc2[4] = {0ull, 0ull, 0ull, 0ull};
#pragma unroll
    for (int k = 0; k < IN_DIM; k++) {
        const float w = W1[k * HID + t];
        const unsigned long long w2 = pack2(w, w);
#pragma unroll
        for (int jj = 0; jj < 4; jj++) {
            const unsigned long long xv =
                *(const unsigned long long*)&xst[k][jj * 2];
            acc2[jj] = ffma2(xv, w2, acc2[jj]);
        }
    }

    float accf[8];
#pragma unroll
    for (int jj = 0; jj < 4; jj++) unpack2(acc2[jj], accf[jj * 2], accf[jj * 2 + 1]);

    const float vas = as1[t], vad = ad1[t];
#pragma unroll
    for (int j = 0; j < 8; j++) {
        g_h1[(n0 + j) * HID + t] = accf[j];
        float vs = accf[j] * vas, vd = accf[j] * vad;
#pragma unroll
        for (int o = 8; o; o >>= 1) {
            vs += __shfl_xor_sync(0xffffffffu, vs, o);
            vd += __shfl_xor_sync(0xffffffffu, vd, o);
        }
        if ((t & 15) == 0) {
            g_a1s[(n0 + j) * HEADS + (t >> 4)] = vs;
            g_a1d[(n0 + j) * HEADS + (t >> 4)] = vd;
        }
    }
}

// ---------------- K3: CSR layer1 aggregation, 4-edge groups -------------------
// lane roles: channels = lane*4..+3 (head hq=lane>>2); exp producer for
// (edge j0+(lane>>3), head lane&7).
__global__ void k3_agg1() {
    const int d = (blockIdx.x * blockDim.x + threadIdx.x) >> 5;
    const int lane = threadIdx.x & 31;
    if (d >= NN) return;

    const float a1d_h = (lane < 8) ? g_a1d[d * HEADS + lane] : 0.f;
    const float a1d_all = __shfl_sync(0xffffffffu, a1d_h, lane & 7);
    const int hq = lane >> 2;
    const int esel = lane >> 3;
    const int hsel = lane & 7;

    const int p0 = g_ptr[d], p1 = g_ptr[d + 1];
    float4 acc = make_float4(0.f, 0.f, 0.f, 0.f);
    float den_part = 0.f;

    for (int base = p0; base < p1; base += 32) {
        const int cnt = min(32, p1 - base);
        int s_r = 0;
        if (lane < cnt) s_r = __ldg(&g_srcs[base + lane]);
        for (int j0 = 0; j0 < cnt; j0 += 4) {
            const int j = j0 + esel;
            const int se = __shfl_sync(0xffffffffu, s_r, j & 31);
            float ex = 0.f;
            if (j < cnt)
                ex = __expf(leaky(__ldg(&g_a1s[se * HEADS + hsel]) + a1d_all));
            den_part += ex;
#pragma unroll
            for (int e2 = 0; e2 < 4; e2++) {
                const float exh = __shfl_sync(0xffffffffu, ex, (e2 << 3) | hq);
                const int s2 = __shfl_sync(0xffffffffu, s_r, (j0 + e2) & 31);
                const float4 hv = *(const float4*)&g_h1[s2 * HID + (lane << 2)];
                acc.x += hv.x * exh;
                acc.y += hv.y * exh;
                acc.z += hv.z * exh;
                acc.w += hv.w * exh;
            }
        }
    }
    // lanes e*8+h hold den partial for head h: fold e
    den_part += __shfl_xor_sync(0xffffffffu, den_part, 8);
    den_part += __shfl_xor_sync(0xffffffffu, den_part, 16);
    const float den = __shfl_sync(0xffffffffu, den_part, hq);
    const float inv = 1.f / (den + 1e-16f);
    acc.x *= inv; acc.y *= inv; acc.z *= inv; acc.w *= inv;
    *(float4*)&g_out1[d * HID + (lane << 2)] = acc;
}

// ---------------- K4: h2 = elu(out1+b1) @ W2 (FFMA2) + attention dots --------
// 64 threads (= out channel), 8 nodes per block.
__global__ void k4_gemm2(const float* __restrict__ W2, const float* __restrict__ b1,
                         const float* __restrict__ as2, const float* __restrict__ ad2) {
    __shared__ __align__(16) float hst[HID][8];      // [k][node]
    __shared__ float rbs[2][8], rbd[2][8];
    const int t = threadIdx.x;
    const int n0 = blockIdx.x * 8;

    for (int i = t; i < 8 * HID; i += 64) {
        const int j = i >> 7, k = i & 127;
        float v = g_out1[n0 * HID + i] + b1[k];
        hst[k][j] = v > 0.f ? v : (__expf(v) - 1.f);
    }
    __syncthreads();

    unsigned long long acc2[4] = {0ull, 0ull, 0ull, 0ull};
#pragma unroll
    for (int k = 0; k < HID; k++) {
        const float w = W2[k * OUT_DIM + t];
        const unsigned long long w2 = pack2(w, w);
#pragma unroll
        for (int jj = 0; jj < 4; jj++) {
            const unsigned long long xv =
                *(const unsigned long long*)&hst[k][jj * 2];
            acc2[jj] = ffma2(xv, w2, acc2[jj]);
        }
    }

    float accf[8];
#pragma unroll
    for (int jj = 0; jj < 4; jj++) unpack2(acc2[jj], accf[jj * 2], accf[jj * 2 + 1]);

    const float vas = as2[t], vad = ad2[t];
    const int wid = t >> 5;
#pragma unroll
    for (int j = 0; j < 8; j++) {
        g_h2[(n0 + j) * OUT_DIM + t] = accf[j];
        float vs = accf[j] * vas, vd = accf[j] * vad;
#pragma unroll
        for (int o = 16; o; o >>= 1) {
            vs += __shfl_xor_sync(0xffffffffu, vs, o);
            vd += __shfl_xor_sync(0xffffffffu, vd, o);
        }
        if ((t & 31) == 0) { rbs[wid][j] = vs; rbd[wid][j] = vd; }
    }
    __syncthreads();
    if (t < 8) {
        g_a2s[n0 + t] = rbs[0][t] + rbs[1][t];
        g_a2d[n0 + t] = rbd[0][t] + rbd[1][t];
    }
}

// ---------------- K6: CSR layer2 aggregation + bias + log_softmax -------------
// warp per dst node; lane owns 2 channels; 4-edge unrolled inner loop.
__global__ void k6_lsm(const float* __restrict__ b2, float* __restrict__ out) {
    const int d = (blockIdx.x * blockDim.x + threadIdx.x) >> 5;
    const int lane = threadIdx.x & 31;
    if (d >= NN) return;

    const float a2d_d = g_a2d[d];
    const int p0 = g_ptr[d], p1 = g_ptr[d + 1];
    float2 acc = make_float2(0.f, 0.f);
    float den = 0.f;

    for (int base = p0; base < p1; base += 32) {
        const int cnt = min(32, p1 - base);
        int s_r = 0;
        float e_r = 0.f;
        if (lane < cnt) {
            s_r = __ldg(&g_srcs[base + lane]);
            e_r = __expf(leaky(__ldg(&g_a2s[s_r]) + a2d_d));
            den += e_r;
        }
        for (int j0 = 0; j0 < cnt; j0 += 4) {
#pragma unroll
            for (int e2 = 0; e2 < 4; e2++) {
                const int jj = (j0 + e2) & 31;
                const float ex = __shfl_sync(0xffffffffu, e_r, jj);
                const int s = __shfl_sync(0xffffffffu, s_r, jj);
                const float2 hv = *(const float2*)&g_h2[s * OUT_DIM + lane * 2];
                acc.x += hv.x * ex;
                acc.y += hv.y * ex;
            }
        }
    }
#pragma unroll
    for (int o = 16; o; o >>= 1) den += __shfl_xor_sync(0xffffffffu, den, o);
    const float inv = 1.f / (den + 1e-16f);

    float vx = acc.x * inv + b2[lane * 2];
    float vy = acc.y * inv + b2[lane * 2 + 1];
    float m = fmaxf(vx, vy);
#pragma unroll
    for (int o = 16; o; o >>= 1) m = fmaxf(m, __shfl_xor_sync(0xffffffffu, m, o));
    float ssum = expf(vx - m) + expf(vy - m);
#pragma unroll
    for (int o = 16; o; o >>= 1) ssum += __shfl_xor_sync(0xffffffffu, ssum, o);
    const float lse = m + logf(ssum);
    *(float2*)&out[d * OUT_DIM + lane * 2] = make_float2(vx - lse, vy - lse);
}

// ---------------- launch ----------------
extern "C" void kernel_launch(void* const* d_in, const int* in_sizes, int n_in,
                              void* d_out, int out_size) {
    const float* x   = (const float*)d_in[0];
    const void*  ei  = d_in[1];
    const float* W1  = (const float*)d_in[2];
    const float* as1 = (const float*)d_in[3];
    const float* ad1 = (const float*)d_in[4];
    const float* b1  = (const float*)d_in[5];
    const float* W2  = (const float*)d_in[6];
    const float* as2 = (const float*)d_in[7];
    const float* ad2 = (const float*)d_in[8];
    const float* b2  = (const float*)d_in[9];
    float* out = (float*)d_out;

    void* pdeg;
    cudaGetSymbolAddress(&pdeg, g_deg);
    cudaMemsetAsync(pdeg, 0, sizeof(int) * NN);

    k0_detect<<<1, 256>>>((const long long*)ei);
    k0_decode<<<(ET + 255) / 256, 256>>>(ei);
    k0_scan<<<1, SCAN_T>>>();
    k0_scatter<<<(ET + 255) / 256, 256>>>();
    k1_gemm1<<<(NN + 7) / 8, 128>>>(x, W1, as1, ad1);
    k3_agg1<<<(NN + 7) / 8, 256>>>();
    k4_gemm2<<<(NN + 7) / 8, 64>>>(W2, b1, as2, ad2);
    k6_lsm<<<(NN + 7) / 8, 256>>>(b2, out);
}